// round 5
// baseline (speedup 1.0000x reference)
#include <cuda_runtime.h>
#include <cuda_bf16.h>

// Single fused persistent kernel, FULL occupancy (8 CTAs/SM guaranteed by
// __launch_bounds__(256, 8); grid = 8 * numSMs -> single co-resident wave,
// so the software grid barrier cannot deadlock).
//
// Closed-form: per_pair = cos^2(1-cos^2) = (1 - cos(4*dTheta))/8.
// Per node v with m unit slots, C = sum cos4t, S = sum sin4t:
//   sum over unit-slot pairs = (m^2 - C^2 - S^2)/16
// Denominator P = sum_v n(n-1)/2 over ALL slots. loss = sum_v(...)/(16*P).
// All state self-cleaning for graph replay.

#define NT 256
#define MAXN 65536

__device__ float4 g_CSW[MAXN];          // {C, S, W(unit cnt), Z(zero cnt)}
__device__ double g_num;
__device__ double g_pairs;
__device__ unsigned g_count;            // barrier arrival
__device__ volatile unsigned g_release; // barrier release flag
__device__ unsigned g_done;             // finalize counter

__device__ __forceinline__ void red_v4(float4* addr, float a, float b, float c, float d) {
    asm volatile("red.global.add.v4.f32 [%0], {%1, %2, %3, %4};"
                 :: "l"(addr), "f"(a), "f"(b), "f"(c), "f"(d) : "memory");
}

__device__ __forceinline__ void do_edge(const float2* __restrict__ pos, int a, int b) {
    float2 pa = __ldg(pos + a);
    float2 pb = __ldg(pos + b);
    float dx = pb.x - pa.x;
    float dy = pb.y - pa.y;
    float n2 = dx * dx + dy * dy;
    float c4, s4, w, z;
    if (n2 > 0.f) {
        float inv = rsqrtf(n2);
        float c = dx * inv, s = dy * inv;
        float c2 = c * c - s * s;
        float s2 = 2.f * c * s;
        c4 = c2 * c2 - s2 * s2;
        s4 = 2.f * c2 * s2;
        w = 1.f; z = 0.f;
    } else {
        c4 = 0.f; s4 = 0.f; w = 0.f; z = 1.f;
    }
    red_v4(&g_CSW[a], c4, s4, w, z);
    red_v4(&g_CSW[b], c4, s4, w, z);
}

__global__ void __launch_bounds__(NT, 8)
fused_kernel(const float2* __restrict__ pos,
             const int* __restrict__ src,
             const int* __restrict__ dst,
             int E, int N, float* __restrict__ out) {
    const int tid = blockIdx.x * NT + threadIdx.x;
    const int nthreads = gridDim.x * NT;

    // ---- Phase 1: edges, grid-stride, coalesced index loads ----
    for (int e = tid; e < E; e += nthreads) {
        do_edge(pos, src[e], dst[e]);
    }

    // ---- Grid barrier (single co-resident wave) ----
    __syncthreads();
    if (threadIdx.x == 0) {
        __threadfence();
        if (atomicAdd(&g_count, 1u) == (unsigned)(gridDim.x - 1)) {
            g_count = 0u;
            __threadfence();
            g_release = 1u;
        } else {
            while (g_release == 0u) { __nanosleep(64); }
        }
        __threadfence();   // acquire: phase-1 reductions now visible
    }
    __syncthreads();

    // ---- Phase 2: per-node closed form + self-clean ----
    double num = 0.0, p = 0.0;
    for (int i = tid; i < N; i += nthreads) {
        float4 v = g_CSW[i];
        g_CSW[i] = make_float4(0.f, 0.f, 0.f, 0.f);
        num += (double)v.z * (double)v.z
             - (double)v.x * (double)v.x
             - (double)v.y * (double)v.y;
        double nn = (double)(v.z + v.w);
        p += 0.5 * nn * (nn - 1.0);
    }

    // ---- Block reduce ----
    #pragma unroll
    for (int off = 16; off > 0; off >>= 1) {
        num += __shfl_down_sync(0xffffffffu, num, off);
        p   += __shfl_down_sync(0xffffffffu, p, off);
    }
    __shared__ double sh_num[8];
    __shared__ double sh_p[8];
    int lane = threadIdx.x & 31;
    int wid  = threadIdx.x >> 5;
    if (lane == 0) { sh_num[wid] = num; sh_p[wid] = p; }
    __syncthreads();
    if (wid == 0) {
        num = (lane < 8) ? sh_num[lane] : 0.0;
        p   = (lane < 8) ? sh_p[lane]   : 0.0;
        #pragma unroll
        for (int off = 4; off > 0; off >>= 1) {
            num += __shfl_down_sync(0xffffffffu, num, off);
            p   += __shfl_down_sync(0xffffffffu, p, off);
        }
        if (lane == 0 && (num != 0.0 || p != 0.0)) {
            atomicAdd(&g_num, num);
            atomicAdd(&g_pairs, p);
        }
    }
    __syncthreads();

    // ---- Finalize (last block) ----
    if (threadIdx.x == 0) {
        __threadfence();
        if (atomicAdd(&g_done, 1u) == (unsigned)(gridDim.x - 1)) {
            double total_num   = atomicAdd(&g_num, 0.0);    // strong L2 reads
            double total_pairs = atomicAdd(&g_pairs, 0.0);
            double denom = 16.0 * total_pairs;
            out[0] = (denom > 0.0) ? (float)(total_num / denom) : 0.0f;
            // reset all state for next graph replay
            g_num = 0.0;
            g_pairs = 0.0;
            g_done = 0u;
            g_release = 0u;
            __threadfence();
        }
    }
}

extern "C" void kernel_launch(void* const* d_in, const int* in_sizes, int n_in,
                              void* d_out, int out_size) {
    const float* pos = (const float*)d_in[0];       // (1, N, 2)
    const int* edge_index = (const int*)d_in[2];    // (2, E)
    int N = in_sizes[0] / 2;
    int E = in_sizes[2] / 2;
    const int* src = edge_index;
    const int* dst = edge_index + E;
    float* out = (float*)d_out;

    int sm_count = 148;
    cudaDeviceGetAttribute(&sm_count, cudaDevAttrMultiProcessorCount, 0);
    int nb = sm_count * 8;   // single co-resident wave (launch_bounds(256,8))

    fused_kernel<<<nb, NT>>>((const float2*)pos, src, dst, E, N, out);
}

// round 6
// speedup vs baseline: 1.0025x; 1.0025x over previous
#include <cuda_runtime.h>
#include <cuda_fp16.h>
#include <cuda_bf16.h>

// Two-kernel structure (fusion regressed: software grid barrier costs more
// than a graph-replay launch gap).
//
// Closed-form: per_pair = cos^2(1-cos^2) = (1 - cos(4*dTheta))/8.
// Per node v: sum over unit-slot pairs = (m^2 - C^2 - S^2)/16,
//   C = sum cos4t, S = sum sin4t over unit slots, m = unit-slot count.
// Denominator P = sum_v n(n-1)/2 over ALL slots (n = degree incl. zero-length
// self-loop slots). loss = sum_v(m^2-C^2-S^2) / (16*P).
//
// Atomic-lane-word diet (the measured bottleneck): per endpoint
//   red.global.add.noftz.f16x2  -> (C,S) in ONE 32-bit word
//   red.global.add.u32          -> deg + (zero_cnt << 16) in ONE word
// = 2 lane-words vs Round 2's 4 (red.v4.f32). State self-cleans in reduce.

#define MAXN 65536

__device__ __half2  g_CS[MAXN];    // (C, S) half2 accumulators
__device__ unsigned g_DZ[MAXN];    // deg (low16) | zero-slot count (high16)
__device__ double g_num;
__device__ double g_pairs;
__device__ unsigned g_done;

__device__ __forceinline__ void red_h2(__half2* addr, unsigned packed) {
    asm volatile("red.global.add.noftz.f16x2 [%0], %1;"
                 :: "l"(addr), "r"(packed) : "memory");
}

__device__ __forceinline__ void red_u32(unsigned* addr, unsigned v) {
    asm volatile("red.global.add.u32 [%0], %1;"
                 :: "l"(addr), "r"(v) : "memory");
}

__global__ void edge_kernel(const float2* __restrict__ pos,
                            const int* __restrict__ src,
                            const int* __restrict__ dst,
                            int E) {
    int e = blockIdx.x * blockDim.x + threadIdx.x;
    if (e >= E) return;
    int a = src[e];
    int b = dst[e];
    float2 pa = __ldg(pos + a);
    float2 pb = __ldg(pos + b);
    float dx = pb.x - pa.x;
    float dy = pb.y - pa.y;
    float n2 = dx * dx + dy * dy;

    if (n2 > 0.f) {
        float inv = rsqrtf(n2);
        float c = dx * inv, s = dy * inv;
        float c2 = c * c - s * s;
        float s2 = 2.f * c * s;
        float c4 = c2 * c2 - s2 * s2;
        float s4 = 2.f * c2 * s2;
        __half2 h = __floats2half2_rn(c4, s4);
        unsigned packed = *reinterpret_cast<unsigned*>(&h);
        red_h2(&g_CS[a], packed);
        red_h2(&g_CS[b], packed);
        red_u32(&g_DZ[a], 1u);
        red_u32(&g_DZ[b], 1u);
    } else {
        // zero-length slot: counts toward degree, flagged in high half
        red_u32(&g_DZ[a], 0x10001u);
        red_u32(&g_DZ[b], 0x10001u);
    }
}

__global__ void reduce_finalize_kernel(float* __restrict__ out, int n) {
    int i = blockIdx.x * blockDim.x + threadIdx.x;
    double num = 0.0, p = 0.0;
    if (i < n) {
        __half2 cs = g_CS[i];
        unsigned dz = g_DZ[i];
        // self-clean for next graph replay
        g_CS[i] = __half2(__float2half(0.f), __float2half(0.f));
        g_DZ[i] = 0u;

        float C = __low2float(cs);
        float S = __high2float(cs);
        int deg = (int)(dz & 0xffffu);
        int z   = (int)(dz >> 16);
        double m = (double)(deg - z);
        num = m * m - (double)C * (double)C - (double)S * (double)S;
        p = 0.5 * (double)deg * (double)(deg - 1);
    }

    #pragma unroll
    for (int off = 16; off > 0; off >>= 1) {
        num += __shfl_down_sync(0xffffffffu, num, off);
        p   += __shfl_down_sync(0xffffffffu, p, off);
    }

    __shared__ double sh_num[8];
    __shared__ double sh_p[8];
    int lane = threadIdx.x & 31;
    int wid  = threadIdx.x >> 5;
    if (lane == 0) { sh_num[wid] = num; sh_p[wid] = p; }
    __syncthreads();

    if (wid == 0) {
        num = (lane < 8) ? sh_num[lane] : 0.0;
        p   = (lane < 8) ? sh_p[lane]   : 0.0;
        #pragma unroll
        for (int off = 4; off > 0; off >>= 1) {
            num += __shfl_down_sync(0xffffffffu, num, off);
            p   += __shfl_down_sync(0xffffffffu, p, off);
        }
        if (lane == 0) {
            atomicAdd(&g_num, num);
            atomicAdd(&g_pairs, p);
            __threadfence();
            if (atomicAdd(&g_done, 1u) == gridDim.x - 1) {
                double total_num   = atomicAdd(&g_num, 0.0);
                double total_pairs = atomicAdd(&g_pairs, 0.0);
                double denom = 16.0 * total_pairs;
                out[0] = (denom > 0.0) ? (float)(total_num / denom) : 0.0f;
                g_num = 0.0;
                g_pairs = 0.0;
                g_done = 0u;
                __threadfence();
            }
        }
    }
}

extern "C" void kernel_launch(void* const* d_in, const int* in_sizes, int n_in,
                              void* d_out, int out_size) {
    const float* pos = (const float*)d_in[0];       // (1, N, 2)
    const int* edge_index = (const int*)d_in[2];    // (2, E)
    int N = in_sizes[0] / 2;
    int E = in_sizes[2] / 2;
    const int* src = edge_index;
    const int* dst = edge_index + E;
    float* out = (float*)d_out;

    int tb = 256;
    edge_kernel<<<(E + tb - 1) / tb, tb>>>((const float2*)pos, src, dst, E);
    reduce_finalize_kernel<<<(N + tb - 1) / tb, tb>>>(out, N);
}

// round 7
// speedup vs baseline: 1.5009x; 1.4972x over previous
#include <cuda_runtime.h>
#include <cuda_bf16.h>

// Round-2 structure (proven 19.2us): edge scatter via ONE red.global.add.v4.f32
// per endpoint (op count, not word count, is the LTS reduction cost — R6 showed
// 2 narrow ops/endpoint is slower than 1 wide op). Changes this round:
//   1. reduce kernel hot path in fp32 (FP64 only at block level)
//   2. PDL: reduce kernel launches early, grid-dependency-syncs before reading.
//
// Closed-form: per_pair = cos^2(1-cos^2) = (1 - cos(4*dTheta))/8.
// Per node v: sum over unit-slot pairs = (m^2 - C^2 - S^2)/16,
//   C = sum cos4t, S = sum sin4t, m = unit slot count.
// P = sum_v n(n-1)/2 over ALL slots (n = degree incl. zero-length slots).
// loss = sum_v(m^2-C^2-S^2) / (16*P). State self-cleans each run.

#define MAXN 65536

__device__ float4 g_CSW[MAXN];   // {C, S, W(unit cnt), Z(zero cnt)}
__device__ double g_num;
__device__ double g_pairs;
__device__ unsigned g_done;

__device__ __forceinline__ void red_v4(float4* addr, float a, float b, float c, float d) {
    asm volatile("red.global.add.v4.f32 [%0], {%1, %2, %3, %4};"
                 :: "l"(addr), "f"(a), "f"(b), "f"(c), "f"(d) : "memory");
}

__global__ void edge_kernel(const float2* __restrict__ pos,
                            const int* __restrict__ src,
                            const int* __restrict__ dst,
                            int E) {
    int e = blockIdx.x * blockDim.x + threadIdx.x;
    if (e < E) {
        int a = src[e];
        int b = dst[e];
        float2 pa = __ldg(pos + a);
        float2 pb = __ldg(pos + b);
        float dx = pb.x - pa.x;
        float dy = pb.y - pa.y;
        float n2 = dx * dx + dy * dy;

        float c4, s4, w, z;
        if (n2 > 0.f) {
            float inv = rsqrtf(n2);
            float c = dx * inv, s = dy * inv;
            float c2 = c * c - s * s;
            float s2 = 2.f * c * s;
            c4 = c2 * c2 - s2 * s2;
            s4 = 2.f * c2 * s2;
            w = 1.f; z = 0.f;
        } else {
            c4 = 0.f; s4 = 0.f; w = 0.f; z = 1.f;
        }
        red_v4(&g_CSW[a], c4, s4, w, z);
        red_v4(&g_CSW[b], c4, s4, w, z);
    }
#if __CUDA_ARCH__ >= 900
    cudaTriggerProgrammaticLaunchCompletion();
#endif
}

__global__ void reduce_finalize_kernel(float* __restrict__ out, int n) {
#if __CUDA_ARCH__ >= 900
    cudaGridDependencySynchronize();   // edge_kernel results now visible
#endif
    int i = blockIdx.x * blockDim.x + threadIdx.x;
    float num = 0.f, p = 0.f;
    if (i < n) {
        float4 v = g_CSW[i];
        g_CSW[i] = make_float4(0.f, 0.f, 0.f, 0.f);   // self-clean for replay
        num = v.z * v.z - v.x * v.x - v.y * v.y;
        float nn = v.z + v.w;                          // total degree
        p = 0.5f * nn * (nn - 1.f);
    }

    // fp32 warp reduce (single-word shfls)
    #pragma unroll
    for (int off = 16; off > 0; off >>= 1) {
        num += __shfl_down_sync(0xffffffffu, num, off);
        p   += __shfl_down_sync(0xffffffffu, p, off);
    }

    __shared__ double sh_num[8];
    __shared__ double sh_p[8];
    int lane = threadIdx.x & 31;
    int wid  = threadIdx.x >> 5;
    if (lane == 0) { sh_num[wid] = (double)num; sh_p[wid] = (double)p; }
    __syncthreads();

    if (wid == 0) {
        double dnum = (lane < 8) ? sh_num[lane] : 0.0;
        double dp   = (lane < 8) ? sh_p[lane]   : 0.0;
        #pragma unroll
        for (int off = 4; off > 0; off >>= 1) {
            dnum += __shfl_down_sync(0xffffffffu, dnum, off);
            dp   += __shfl_down_sync(0xffffffffu, dp, off);
        }
        if (lane == 0) {
            atomicAdd(&g_num, dnum);
            atomicAdd(&g_pairs, dp);
            __threadfence();
            if (atomicAdd(&g_done, 1u) == gridDim.x - 1) {
                double total_num   = atomicAdd(&g_num, 0.0);
                double total_pairs = atomicAdd(&g_pairs, 0.0);
                double denom = 16.0 * total_pairs;
                out[0] = (denom > 0.0) ? (float)(total_num / denom) : 0.0f;
                g_num = 0.0;
                g_pairs = 0.0;
                g_done = 0u;
                __threadfence();
            }
        }
    }
}

extern "C" void kernel_launch(void* const* d_in, const int* in_sizes, int n_in,
                              void* d_out, int out_size) {
    const float* pos = (const float*)d_in[0];       // (1, N, 2)
    const int* edge_index = (const int*)d_in[2];    // (2, E)
    int N = in_sizes[0] / 2;
    int E = in_sizes[2] / 2;
    const int* src = edge_index;
    const int* dst = edge_index + E;
    float* out = (float*)d_out;

    const int tb = 256;
    edge_kernel<<<(E + tb - 1) / tb, tb>>>((const float2*)pos, src, dst, E);

    // PDL: allow this launch to begin while edge_kernel drains; the kernel
    // itself grid-dependency-syncs before reading edge results.
    cudaLaunchConfig_t cfg = {};
    cfg.gridDim  = dim3((N + tb - 1) / tb);
    cfg.blockDim = dim3(tb);
    cfg.dynamicSmemBytes = 0;
    cfg.stream = 0;
    cudaLaunchAttribute attr[1];
    attr[0].id = cudaLaunchAttributeProgrammaticStreamSerialization;
    attr[0].val.programmaticStreamSerializationAllowed = 1;
    cfg.attrs = attr;
    cfg.numAttrs = 1;
    cudaLaunchKernelEx(&cfg, reduce_finalize_kernel, out, N);
}